// round 7
// baseline (speedup 1.0000x reference)
#include <cuda_runtime.h>
#include <cstdint>

#define N 8192
#define IN_F 512
#define OUT_F 64
#define NEG_SLOPE 0.01f
#define LOG2E 1.44269504088896340736f

#define TI 128
#define TJ 64
#define SPLIT 8
#define JSPAN (N / SPLIT)     // 1024
#define NT_S (JSPAN / TJ)     // 16

#define PSTR 68   // Ps row stride (words): A-frag banks (4*gid+tid)%32 conflict-free
#define VSTR 72   // Vs row stride (words): B-frag banks (8*tid+gid)%32 conflict-free

// gat dynamic smem layout (bytes); red aliases Ps (used only after mainloop)
#define PS_OFF  0                    // 128*68*4 = 34816
#define VS_OFF  34816                // 64*72*4  = 18432
#define WH2_OFF 53248                // 2*64*4   = 512
#define WH1_OFF 53760                // 128*4    = 512
#define GAT_SMEM 54272

// Scratch (allocation-free rule: device globals)
__device__ __align__(16) float g_WH[N * OUT_F];
__device__ float g_wh1[N];           // pre-scaled by LOG2E
__device__ float g_wh2[N];           // pre-scaled by LOG2E
__device__ float g_M;                // shift, in log2 units
__device__ __align__(16) float g_pacc[SPLIT * N * OUT_F];   // 16 MB partial PV
__device__ float g_psum[SPLIT * N];                         // partial row sums

__device__ __forceinline__ uint32_t su(const void* p) {
    return (uint32_t)__cvta_generic_to_shared(p);
}
#define CP_ASYNC16(dst, src) \
    asm volatile("cp.async.cg.shared.global [%0], [%1], 16;" :: "r"(dst), "l"(src))
#define CP_COMMIT() asm volatile("cp.async.commit_group;" ::: "memory")
#define CP_WAIT0()  asm volatile("cp.async.wait_group 0;" ::: "memory")

// tf32 m16n8k8 tensor-core mma (baseline PTX, valid on sm_103 non-a target)
__device__ __forceinline__ void mma_tf32(float* c, uint32_t a0, uint32_t a1,
                                         uint32_t a2, uint32_t a3,
                                         uint32_t b0, uint32_t b1) {
    asm volatile(
        "mma.sync.aligned.m16n8k8.row.col.f32.tf32.tf32.f32 "
        "{%0,%1,%2,%3}, {%4,%5,%6,%7}, {%8,%9}, {%0,%1,%2,%3};"
        : "+f"(c[0]), "+f"(c[1]), "+f"(c[2]), "+f"(c[3])
        : "r"(a0), "r"(a1), "r"(a2), "r"(a3), "r"(b0), "r"(b1));
}

// ---------------------------------------------------------------------------
// Kernel A: WH = h @ W   [8192,512] @ [512,64]
// 128 blocks x 256 threads, 64 rows/block. h staged transposed so the inner
// loop is 2x LDS.128 (W) + 1x LDS.64 (h) per 16 FMA; f32x2 accumulation.
// ---------------------------------------------------------------------------
#define HSTR 66
__global__ void __launch_bounds__(256) wh_kernel(const float* __restrict__ h,
                                                 const float* __restrict__ W) {
    __shared__ __align__(16) float Wc[64 * 64];     // Wc[k][f]   16 KB
    __shared__ __align__(16) float hT[64 * HSTR];   // hT[k][row] 16.5 KB

    const int t  = threadIdx.x;
    const int f8 = t & 7;        // features f8*8 .. f8*8+7
    const int rg = t >> 3;       // rows 2rg, 2rg+1
    const int r0 = blockIdx.x * 64;

    unsigned long long acc[2][4];
#pragma unroll
    for (int r = 0; r < 2; r++)
#pragma unroll
        for (int q = 0; q < 4; q++) acc[r][q] = 0ull;

    for (int kc = 0; kc < IN_F; kc += 64) {
        __syncthreads();
#pragma unroll
        for (int i = 0; i < 4; i++) {            // Wc: 1024 float4
            int idx = t + i * 256;
            ((float4*)Wc)[idx] = ((const float4*)W)[(size_t)(kc + (idx >> 4)) * 16 + (idx & 15)];
        }
#pragma unroll
        for (int i = 0; i < 4; i++) {            // hT: 64 rows x 64 k, transposed
            int idx = t + i * 256;
            int row = idx >> 4, k4 = idx & 15;
            float4 hv = ((const float4*)h)[(size_t)(r0 + row) * (IN_F / 4) + (kc >> 2) + k4];
            hT[(k4 * 4 + 0) * HSTR + row] = hv.x;
            hT[(k4 * 4 + 1) * HSTR + row] = hv.y;
            hT[(k4 * 4 + 2) * HSTR + row] = hv.z;
            hT[(k4 * 4 + 3) * HSTR + row] = hv.w;
        }
        __syncthreads();
#pragma unroll 4
        for (int k = 0; k < 64; k++) {
            ulonglong2 wa = *(const ulonglong2*)&Wc[k * 64 + f8 * 8];
            ulonglong2 wb = *(const ulonglong2*)&Wc[k * 64 + f8 * 8 + 4];
            float2 hv = *(const float2*)&hT[k * HSTR + rg * 2];
            unsigned long long h0d, h1d;
            asm("mov.b64 %0, {%1, %1};" : "=l"(h0d) : "f"(hv.x));
            asm("mov.b64 %0, {%1, %1};" : "=l"(h1d) : "f"(hv.y));
            asm("fma.rn.f32x2 %0, %1, %2, %0;" : "+l"(acc[0][0]) : "l"(h0d), "l"(wa.x));
            asm("fma.rn.f32x2 %0, %1, %2, %0;" : "+l"(acc[0][1]) : "l"(h0d), "l"(wa.y));
            asm("fma.rn.f32x2 %0, %1, %2, %0;" : "+l"(acc[0][2]) : "l"(h0d), "l"(wb.x));
            asm("fma.rn.f32x2 %0, %1, %2, %0;" : "+l"(acc[0][3]) : "l"(h0d), "l"(wb.y));
            asm("fma.rn.f32x2 %0, %1, %2, %0;" : "+l"(acc[1][0]) : "l"(h1d), "l"(wa.x));
            asm("fma.rn.f32x2 %0, %1, %2, %0;" : "+l"(acc[1][1]) : "l"(h1d), "l"(wa.y));
            asm("fma.rn.f32x2 %0, %1, %2, %0;" : "+l"(acc[1][2]) : "l"(h1d), "l"(wb.x));
            asm("fma.rn.f32x2 %0, %1, %2, %0;" : "+l"(acc[1][3]) : "l"(h1d), "l"(wb.y));
        }
    }
#pragma unroll
    for (int r = 0; r < 2; r++) {
        float v0, v1, v2, v3, v4, v5, v6, v7;
        asm("mov.b64 {%0, %1}, %2;" : "=f"(v0), "=f"(v1) : "l"(acc[r][0]));
        asm("mov.b64 {%0, %1}, %2;" : "=f"(v2), "=f"(v3) : "l"(acc[r][1]));
        asm("mov.b64 {%0, %1}, %2;" : "=f"(v4), "=f"(v5) : "l"(acc[r][2]));
        asm("mov.b64 {%0, %1}, %2;" : "=f"(v6), "=f"(v7) : "l"(acc[r][3]));
        float* dst = g_WH + (size_t)(r0 + rg * 2 + r) * OUT_F + f8 * 8;
        *(float4*)dst = make_float4(v0, v1, v2, v3);
        *(float4*)(dst + 4) = make_float4(v4, v5, v6, v7);
    }
}

// ---------------------------------------------------------------------------
// Kernel B: wh1/wh2 row dots, pre-scaled by LOG2E (softmax in exp2 domain)
// ---------------------------------------------------------------------------
__global__ void __launch_bounds__(256) attn_vec_kernel(const float* __restrict__ a) {
    const int warp = threadIdx.x >> 5;
    const int lane = threadIdx.x & 31;
    const int r = blockIdx.x * 8 + warp;

    float2 v = ((const float2*)(g_WH + (size_t)r * OUT_F))[lane];
    float d1 = v.x * a[2 * lane] + v.y * a[2 * lane + 1];
    float d2 = v.x * a[OUT_F + 2 * lane] + v.y * a[OUT_F + 2 * lane + 1];
#pragma unroll
    for (int off = 16; off > 0; off >>= 1) {
        d1 += __shfl_xor_sync(0xFFFFFFFFu, d1, off);
        d2 += __shfl_xor_sync(0xFFFFFFFFu, d2, off);
    }
    if (lane == 0) {
        g_wh1[r] = d1 * LOG2E;
        g_wh2[r] = d2 * LOG2E;
    }
}

// ---------------------------------------------------------------------------
// Kernel B2: global softmax shift M = max(wh1) + max(wh2)  (log2 domain)
// ---------------------------------------------------------------------------
__global__ void __launch_bounds__(1024) max_kernel() {
    __shared__ float s1[1024], s2[1024];
    const int t = threadIdx.x;
    float m1 = -1e30f, m2 = -1e30f;
#pragma unroll
    for (int i = 0; i < N / 1024; i++) {
        m1 = fmaxf(m1, g_wh1[t + i * 1024]);
        m2 = fmaxf(m2, g_wh2[t + i * 1024]);
    }
    s1[t] = m1; s2[t] = m2;
    __syncthreads();
    for (int s = 512; s > 0; s >>= 1) {
        if (t < s) {
            s1[t] = fmaxf(s1[t], s1[t + s]);
            s2[t] = fmaxf(s2[t], s2[t + s]);
        }
        __syncthreads();
    }
    if (t == 0) g_M = s1[0] + s2[0];
}

// ---------------------------------------------------------------------------
// Kernel C: scores (SIMT, exp2) -> PV matmul (tf32 mma.sync)
//  grid (N/TI, SPLIT) = (64, 8). Warp w: rows (w>>1)*32..+32 (two m16 blocks
//  sharing B-fragments), cols (w&1)*32..+32.
// ---------------------------------------------------------------------------
__global__ void __launch_bounds__(256, 2) gat_kernel(const int* __restrict__ adj) {
    extern __shared__ __align__(16) char sm[];
    float* Ps   = (float*)(sm + PS_OFF);
    float* Vs   = (float*)(sm + VS_OFF);
    float* wh2s = (float*)(sm + WH2_OFF);
    float* wh1s = (float*)(sm + WH1_OFF);
    float* red  = (float*)sm;            // aliases Ps; used only after mainloop

    const int t    = threadIdx.x;
    const int ry   = t >> 4;            // score rows: ry + 16k, k=0..7
    const int jb   = (t & 15) * 4;      // score cols within tile
    const int lane = t & 31;
    const int warp = t >> 5;
    const int gid  = lane >> 2;
    const int tid  = lane & 3;
    const int rs   = (warp >> 1) * 32;  // mma row stripe (2 m16 blocks)
    const int ch   = (warp & 1) * 32;   // mma col half
    const int i0   = blockIdx.x * TI;
    const int sp   = blockIdx.y;
    const int jbase = sp * JSPAN;

    if (t < TI) wh1s[t] = g_wh1[i0 + t];
    if (t < 16) CP_ASYNC16(su(&wh2s[t * 4]), (const void*)(g_wh2 + jbase + t * 4));
    CP_COMMIT();

    int4 a4[8];
#pragma unroll
    for (int k = 0; k < 8; k++)
        a4[k] = *(const int4*)(adj + (size_t)(i0 + ry + 16 * k) * N + jbase + jb);

    const float Mv = g_M;
    float sums[8];
#pragma unroll
    for (int k = 0; k < 8; k++) sums[k] = 0.f;
    float c[2][4][4];
#pragma unroll
    for (int rb = 0; rb < 2; rb++)
#pragma unroll
        for (int nt = 0; nt < 4; nt++)
#pragma unroll
            for (int q = 0; q < 4; q++) c[rb][nt][q] = 0.f;

    CP_WAIT0();

    for (int tt = 0; tt < NT_S; ++tt) {
        const int b = tt & 1;
        const int j0 = jbase + tt * TJ;
        __syncthreads();   // mma(tt-1) done -> Ps/Vs free; wh2s[b] visible

        // ---- issue V tile (tt) + wh2 (tt+1) loads ----
#pragma unroll
        for (int i = 0; i < 4; i++) {
            int idx = t + i * 256;
            int row = idx >> 4, cc = idx & 15;
            CP_ASYNC16(su(Vs) + row * (VSTR * 4) + cc * 16,
                       (const void*)(g_WH + (size_t)(j0 + row) * OUT_F + cc * 4));
        }
        if (tt + 1 < NT_S && t < 16)
            CP_ASYNC16(su(&wh2s[(b ^ 1) * 64 + t * 4]), (const void*)(g_wh2 + j0 + TJ + t * 4));
        CP_COMMIT();

        // ---- scores -> Ps, register row sums, adjacency prefetch ----
        const float4 w2 = *(const float4*)&wh2s[b * 64 + jb];
#pragma unroll
        for (int k = 0; k < 8; k++) {
            const int r = ry + 16 * k;
            const float b1 = wh1s[r];
            float e0 = b1 + w2.x; e0 = (e0 > 0.f) ? e0 : NEG_SLOPE * e0;
            float e1 = b1 + w2.y; e1 = (e1 > 0.f) ? e1 : NEG_SLOPE * e1;
            float e2 = b1 + w2.z; e2 = (e2 > 0.f) ? e2 : NEG_SLOPE * e2;
            float e3 = b1 + w2.w; e3 = (e3 > 0.f) ? e3 : NEG_SLOPE * e3;
            float p0 = (a4[k].x > 0) ? exp2f(e0 - Mv) : 0.f;
            float p1 = (a4[k].y > 0) ? exp2f(e1 - Mv) : 0.f;
            float p2 = (a4[k].z > 0) ? exp2f(e2 - Mv) : 0.f;
            float p3 = (a4[k].w > 0) ? exp2f(e3 - Mv) : 0.f;
            sums[k] += (p0 + p1) + (p2 + p3);
            *(float4*)&Ps[r * PSTR + jb] = make_float4(p0, p1, p2, p3);
            if (tt + 1 < NT_S)
                a4[k] = *(const int4*)(adj + (size_t)(i0 + r) * N + j0 + TJ + jb);
        }

        CP_WAIT0();
        __syncthreads();   // Ps + Vs ready

        // ---- tensor-core PV: warp 32x32 output, B-frags shared by 2 m16 blocks ----
#pragma unroll
        for (int k8 = 0; k8 < 8; k8++) {
            const int k0 = k8 * 8;
            uint32_t a[2][4];
#pragma unroll
            for (int rb = 0; rb < 2; rb++) {
                const int rr = rs + rb * 16;
                a[rb][0] = __float_as_uint(Ps[(rr + gid) * PSTR + k0 + tid]);
                a[rb][1] = __float_as_uint(Ps[(rr + gid + 8) * PSTR + k0 + tid]);
                a[rb][2] = __float_as_uint(Ps[(rr + gid) * PSTR + k0 + tid + 4]);
                a[rb][3] = __float_as_uint(Ps[(rr + gid + 8) * PSTR + k0 + tid + 4]);
            }
#pragma unroll
            for (int nt = 0; nt < 4; nt++) {
                uint32_t b0 = __float_as_uint(Vs[(k0 + tid) * VSTR + ch + nt * 8 + gid]);
                uint32_t b1 = __float_as_uint(Vs[(k0 + tid + 4) * VSTR + ch + nt * 8 + gid]);
                mma_tf32(c[0][nt], a[0][0], a[0][1], a[0][2], a[0][3], b0, b1);
                mma_tf32(c[1][nt], a[1][0], a[1][1], a[1][2], a[1][3], b0, b1);
            }
        }
    }

    __syncthreads();   // all mma done before red overwrites Ps region

    // ---- row-sum reduction -> g_psum ----
#pragma unroll
    for (int k = 0; k < 8; k++)
        red[(ry + 16 * k) * 16 + (t & 15)] = sums[k];
    __syncthreads();
    if (t < TI) {
        float s = 0.f;
#pragma unroll
        for (int q = 0; q < 16; q++) s += red[t * 16 + q];
        g_psum[sp * N + i0 + t] = s;
    }

    // ---- store unnormalized partials from mma accumulators ----
#pragma unroll
    for (int rb = 0; rb < 2; rb++) {
        const int row0 = i0 + rs + rb * 16 + gid;
#pragma unroll
        for (int nt = 0; nt < 4; nt++) {
            const int col = ch + nt * 8 + 2 * tid;
            *(float2*)&g_pacc[((size_t)sp * N + row0) * OUT_F + col] =
                make_float2(c[rb][nt][0], c[rb][nt][1]);
            *(float2*)&g_pacc[((size_t)sp * N + row0 + 8) * OUT_F + col] =
                make_float2(c[rb][nt][2], c[rb][nt][3]);
        }
    }
}

// ---------------------------------------------------------------------------
// Kernel D: combine partials, normalize, elu
// ---------------------------------------------------------------------------
__global__ void __launch_bounds__(256) combine_kernel(float* __restrict__ out) {
    const int idx = blockIdx.x * 256 + threadIdx.x;   // N*16 float4 slots
    const int r = idx >> 4;

    float4 a = make_float4(0.f, 0.f, 0.f, 0.f);
    float s = 0.f;
#pragma unroll
    for (int sp = 0; sp < SPLIT; sp++) {
        float4 p = ((const float4*)g_pacc)[(size_t)sp * (N * 16) + idx];
        a.x += p.x; a.y += p.y; a.z += p.z; a.w += p.w;
        s += g_psum[sp * N + r];
    }
    const float inv = 1.f / s;
    float v;
    float4 o;
    v = a.x * inv; o.x = (v > 0.f) ? v : expm1f(v);
    v = a.y * inv; o.y = (v > 0.f) ? v : expm1f(v);
    v = a.z * inv; o.z = (v > 0.f) ? v : expm1f(v);
    v = a.w * inv; o.w = (v > 0.f) ? v : expm1f(v);
    ((float4*)out)[idx] = o;
}

// ---------------------------------------------------------------------------
extern "C" void kernel_launch(void* const* d_in, const int* in_sizes, int n_in,
                              void* d_out, int out_size) {
    const float* h   = nullptr;
    const int*   adj = nullptr;
    const float* W   = nullptr;
    const float* a   = nullptr;
    for (int i = 0; i < n_in; i++) {
        long long sz = in_sizes[i];
        if (sz == (long long)N * IN_F)          h   = (const float*)d_in[i];
        else if (sz == (long long)N * N)        adj = (const int*)d_in[i];
        else if (sz == (long long)IN_F * OUT_F) W   = (const float*)d_in[i];
        else if (sz == 2 * OUT_F)               a   = (const float*)d_in[i];
    }

    cudaFuncSetAttribute(gat_kernel, cudaFuncAttributeMaxDynamicSharedMemorySize, GAT_SMEM);

    wh_kernel<<<N / 64, 256>>>(h, W);
    attn_vec_kernel<<<N / 8, 256>>>(a);
    max_kernel<<<1, 1024>>>();
    gat_kernel<<<dim3(N / TI, SPLIT), 256, GAT_SMEM>>>(adj);
    combine_kernel<<<(N * 16) / 256, 256>>>((float*)d_out);
}

// round 8
// speedup vs baseline: 1.1658x; 1.1658x over previous
#include <cuda_runtime.h>
#include <cstdint>

#define N 8192
#define IN_F 512
#define OUT_F 64
#define NEG_SLOPE 0.01f
#define LOG2E 1.44269504088896340736f

#define TI 64
#define TJ 64
#define SPLIT 16
#define JSPAN (N / SPLIT)     // 512
#define NT_S (JSPAN / TJ)     // 8

#define PSTR 68   // Ps row stride (words): A-frag banks conflict-free
#define VSTR 72   // Vs row stride (words): B-frag banks conflict-free

// Scratch (allocation-free rule: device globals)
__device__ __align__(16) float g_WH[N * OUT_F];
__device__ float g_wh1[N];           // pre-scaled by LOG2E
__device__ float g_wh2[N];           // pre-scaled by LOG2E
__device__ unsigned g_m1u = 0;       // order-preserving-key max of wh1
__device__ unsigned g_m2u = 0;       // order-preserving-key max of wh2
__device__ __align__(16) float g_pacc[SPLIT * N * OUT_F];   // 32 MB partial PV
__device__ float g_psum[SPLIT * N];                         // partial row sums

__device__ __forceinline__ uint32_t su(const void* p) {
    return (uint32_t)__cvta_generic_to_shared(p);
}
#define CP_ASYNC16(dst, src) \
    asm volatile("cp.async.cg.shared.global [%0], [%1], 16;" :: "r"(dst), "l"(src))
#define CP_COMMIT() asm volatile("cp.async.commit_group;" ::: "memory")
#define CP_WAIT0()  asm volatile("cp.async.wait_group 0;" ::: "memory")

// order-preserving float<->unsigned key (monotonic under unsigned compare)
__device__ __forceinline__ unsigned f2key(float x) {
    unsigned b = __float_as_uint(x);
    return (b & 0x80000000u) ? ~b : (b | 0x80000000u);
}
__device__ __forceinline__ float key2f(unsigned u) {
    return __uint_as_float((u & 0x80000000u) ? (u & 0x7FFFFFFFu) : ~u);
}

// tf32 m16n8k8 tensor-core mma (baseline PTX, valid on sm_103 non-a target)
__device__ __forceinline__ void mma_tf32(float* c, uint32_t a0, uint32_t a1,
                                         uint32_t a2, uint32_t a3,
                                         uint32_t b0, uint32_t b1) {
    asm volatile(
        "mma.sync.aligned.m16n8k8.row.col.f32.tf32.tf32.f32 "
        "{%0,%1,%2,%3}, {%4,%5,%6,%7}, {%8,%9}, {%0,%1,%2,%3};"
        : "+f"(c[0]), "+f"(c[1]), "+f"(c[2]), "+f"(c[3])
        : "r"(a0), "r"(a1), "r"(a2), "r"(a3), "r"(b0), "r"(b1));
}

// ---------------------------------------------------------------------------
// Kernel A: WH = h @ W   [8192,512] @ [512,64]
// 128 blocks x 256 threads; block tile 64 rows x 64 feats; thread tile 4x4.
// Outer product: per k, 1 LDS.128 (W frag) + 1 LDS.128 broadcast (h frag),
// 16 MAC as 8 packed f32x2 FMA.
// ---------------------------------------------------------------------------
#define HS 68   // hT row stride (words): mult of 4 (LDS.128-aligned)
__global__ void __launch_bounds__(256) wh_kernel(const float* __restrict__ h,
                                                 const float* __restrict__ W) {
    __shared__ __align__(16) float Wc[64 * 64];   // Wc[k][f]    16 KB
    __shared__ __align__(16) float hT[64 * HS];   // hT[k][row]  17.4 KB

    const int t  = threadIdx.x;
    const int tx = t & 15;       // feats tx*4 .. +3
    const int ty = t >> 4;       // rows  ty*4 .. +3
    const int r0 = blockIdx.x * 64;

    unsigned long long acc[4][2];
#pragma unroll
    for (int r = 0; r < 4; r++) { acc[r][0] = 0ull; acc[r][1] = 0ull; }

    for (int kc = 0; kc < IN_F; kc += 64) {
        __syncthreads();
#pragma unroll
        for (int i = 0; i < 4; i++) {            // Wc: 1024 float4, contiguous
            int idx = t + i * 256;
            ((float4*)Wc)[idx] = ((const float4*)W)[(size_t)(kc + (idx >> 4)) * 16 + (idx & 15)];
        }
#pragma unroll
        for (int i = 0; i < 4; i++) {            // hT: transpose stage
            int idx = t + i * 256;
            int row = idx & 63, kq = idx >> 6;   // kq 0..15 (float4 of k)
            float4 hv = ((const float4*)h)[(size_t)(r0 + row) * (IN_F / 4) + (kc >> 2) + kq];
            hT[(kq * 4 + 0) * HS + row] = hv.x;  // lanes: row stride 1 -> conflict-free
            hT[(kq * 4 + 1) * HS + row] = hv.y;
            hT[(kq * 4 + 2) * HS + row] = hv.z;
            hT[(kq * 4 + 3) * HS + row] = hv.w;
        }
        __syncthreads();
#pragma unroll 4
        for (int k = 0; k < 64; k++) {
            ulonglong2 w = *(const ulonglong2*)&Wc[k * 64 + tx * 4];
            float4 hv = *(const float4*)&hT[k * HS + ty * 4];
            unsigned long long hd;
            asm("mov.b64 %0, {%1, %1};" : "=l"(hd) : "f"(hv.x));
            asm("fma.rn.f32x2 %0, %1, %2, %0;" : "+l"(acc[0][0]) : "l"(hd), "l"(w.x));
            asm("fma.rn.f32x2 %0, %1, %2, %0;" : "+l"(acc[0][1]) : "l"(hd), "l"(w.y));
            asm("mov.b64 %0, {%1, %1};" : "=l"(hd) : "f"(hv.y));
            asm("fma.rn.f32x2 %0, %1, %2, %0;" : "+l"(acc[1][0]) : "l"(hd), "l"(w.x));
            asm("fma.rn.f32x2 %0, %1, %2, %0;" : "+l"(acc[1][1]) : "l"(hd), "l"(w.y));
            asm("mov.b64 %0, {%1, %1};" : "=l"(hd) : "f"(hv.z));
            asm("fma.rn.f32x2 %0, %1, %2, %0;" : "+l"(acc[2][0]) : "l"(hd), "l"(w.x));
            asm("fma.rn.f32x2 %0, %1, %2, %0;" : "+l"(acc[2][1]) : "l"(hd), "l"(w.y));
            asm("mov.b64 %0, {%1, %1};" : "=l"(hd) : "f"(hv.w));
            asm("fma.rn.f32x2 %0, %1, %2, %0;" : "+l"(acc[3][0]) : "l"(hd), "l"(w.x));
            asm("fma.rn.f32x2 %0, %1, %2, %0;" : "+l"(acc[3][1]) : "l"(hd), "l"(w.y));
        }
    }
#pragma unroll
    for (int r = 0; r < 4; r++) {
        float v0, v1, v2, v3;
        asm("mov.b64 {%0, %1}, %2;" : "=f"(v0), "=f"(v1) : "l"(acc[r][0]));
        asm("mov.b64 {%0, %1}, %2;" : "=f"(v2), "=f"(v3) : "l"(acc[r][1]));
        *(float4*)(g_WH + (size_t)(r0 + ty * 4 + r) * OUT_F + tx * 4) =
            make_float4(v0, v1, v2, v3);
    }
}

// ---------------------------------------------------------------------------
// Kernel B: wh1/wh2 row dots (LOG2E-scaled) + global max via key-atomicMax.
// 64 blocks x 256 threads; each warp handles 16 rows.
// ---------------------------------------------------------------------------
__global__ void __launch_bounds__(256) attn_vec_kernel(const float* __restrict__ a) {
    __shared__ float s1[8], s2[8];
    const int warp = threadIdx.x >> 5;
    const int lane = threadIdx.x & 31;

    const float a1a = a[2 * lane], a1b = a[2 * lane + 1];
    const float a2a = a[OUT_F + 2 * lane], a2b = a[OUT_F + 2 * lane + 1];

    float m1 = -1e30f, m2 = -1e30f;
#pragma unroll
    for (int rr = 0; rr < 16; rr++) {
        const int r = blockIdx.x * 128 + rr * 8 + warp;
        float2 v = ((const float2*)(g_WH + (size_t)r * OUT_F))[lane];
        float d1 = v.x * a1a + v.y * a1b;
        float d2 = v.x * a2a + v.y * a2b;
#pragma unroll
        for (int off = 16; off > 0; off >>= 1) {
            d1 += __shfl_xor_sync(0xFFFFFFFFu, d1, off);
            d2 += __shfl_xor_sync(0xFFFFFFFFu, d2, off);
        }
        d1 *= LOG2E; d2 *= LOG2E;
        if (lane == 0) {
            g_wh1[r] = d1;
            g_wh2[r] = d2;
            m1 = fmaxf(m1, d1);
            m2 = fmaxf(m2, d2);
        }
    }
    if (lane == 0) { s1[warp] = m1; s2[warp] = m2; }
    __syncthreads();
    if (threadIdx.x == 0) {
        float b1 = s1[0], b2 = s2[0];
#pragma unroll
        for (int w = 1; w < 8; w++) { b1 = fmaxf(b1, s1[w]); b2 = fmaxf(b2, s2[w]); }
        atomicMax(&g_m1u, f2key(b1));   // idempotent across graph replays
        atomicMax(&g_m2u, f2key(b2));
    }
}

// ---------------------------------------------------------------------------
// Kernel C: scores (SIMT, exp2) -> PV matmul (tf32 mma.sync)
//  grid (N/TI, SPLIT) = (128, 16). Warp w: rows (w>>1)*16..+16, cols (w&1)*32..+32.
// ---------------------------------------------------------------------------
__global__ void __launch_bounds__(256, 3) gat_kernel(const int* __restrict__ adj) {
    __shared__ __align__(16) float Ps[TI * PSTR];       // 17.0 KB scores
    __shared__ __align__(16) float Vs[TJ * VSTR];       // 18.0 KB V tile
    __shared__ __align__(16) float wh2s[2][TJ];
    __shared__ float wh1s[TI];
    __shared__ float red[TI * 16];

    const int t    = threadIdx.x;
    const int ry   = t >> 4;            // score rows: ry + 16k
    const int jb   = (t & 15) * 4;      // score cols within tile
    const int lane = t & 31;
    const int warp = t >> 5;
    const int gid  = lane >> 2;
    const int tid  = lane & 3;
    const int rs   = (warp >> 1) * 16;  // mma row stripe
    const int ch   = (warp & 1) * 32;   // mma col half
    const int i0   = blockIdx.x * TI;
    const int sp   = blockIdx.y;
    const int jbase = sp * JSPAN;

    if (t < TI) wh1s[t] = g_wh1[i0 + t];
    if (t < 16) CP_ASYNC16(su(&wh2s[0][t * 4]), (const void*)(g_wh2 + jbase + t * 4));
    CP_COMMIT();

    int4 a4[4];
#pragma unroll
    for (int k = 0; k < 4; k++)
        a4[k] = *(const int4*)(adj + (size_t)(i0 + ry + 16 * k) * N + jbase + jb);

    const float Mv = key2f(g_m1u) + key2f(g_m2u);   // log2-domain shift
    float sums[4] = {0.f, 0.f, 0.f, 0.f};
    float c[4][4];
#pragma unroll
    for (int nt = 0; nt < 4; nt++)
#pragma unroll
        for (int q = 0; q < 4; q++) c[nt][q] = 0.f;

    CP_WAIT0();   // wh2s[0] resident (visibility via first in-loop sync)

    for (int tt = 0; tt < NT_S; ++tt) {
        const int b = tt & 1;
        const int j0 = jbase + tt * TJ;
        __syncthreads();   // mma(tt-1) done -> Ps/Vs free; wh2s[b] visible

        // ---- issue V tile (tt) + wh2 (tt+1) loads ----
#pragma unroll
        for (int i = 0; i < 4; i++) {
            int idx = t + i * 256;
            int row = idx >> 4, cc = idx & 15;
            CP_ASYNC16(su(Vs) + row * (VSTR * 4) + cc * 16,
                       (const void*)(g_WH + (size_t)(j0 + row) * OUT_F + cc * 4));
        }
        if (tt + 1 < NT_S && t < 16)
            CP_ASYNC16(su(&wh2s[b ^ 1][t * 4]), (const void*)(g_wh2 + j0 + TJ + t * 4));
        CP_COMMIT();

        // ---- scores -> Ps, register row sums, adjacency prefetch ----
        const float4 w2 = *(const float4*)&wh2s[b][jb];
#pragma unroll
        for (int k = 0; k < 4; k++) {
            const int r = ry + 16 * k;
            const float b1 = wh1s[r];
            float e0 = b1 + w2.x; e0 = (e0 > 0.f) ? e0 : NEG_SLOPE * e0;
            float e1 = b1 + w2.y; e1 = (e1 > 0.f) ? e1 : NEG_SLOPE * e1;
            float e2 = b1 + w2.z; e2 = (e2 > 0.f) ? e2 : NEG_SLOPE * e2;
            float e3 = b1 + w2.w; e3 = (e3 > 0.f) ? e3 : NEG_SLOPE * e3;
            float p0 = (a4[k].x > 0) ? exp2f(e0 - Mv) : 0.f;
            float p1 = (a4[k].y > 0) ? exp2f(e1 - Mv) : 0.f;
            float p2 = (a4[k].z > 0) ? exp2f(e2 - Mv) : 0.f;
            float p3 = (a4[k].w > 0) ? exp2f(e3 - Mv) : 0.f;
            sums[k] += (p0 + p1) + (p2 + p3);
            *(float4*)&Ps[r * PSTR + jb] = make_float4(p0, p1, p2, p3);
            if (tt + 1 < NT_S)
                a4[k] = *(const int4*)(adj + (size_t)(i0 + r) * N + j0 + TJ + jb);
        }

        CP_WAIT0();
        __syncthreads();   // Ps + Vs ready

        // ---- tensor-core PV: per warp 16x32 output, k=64 in chunks of 8 ----
#pragma unroll
        for (int k8 = 0; k8 < 8; k8++) {
            const int k0 = k8 * 8;
            uint32_t a0 = __float_as_uint(Ps[(rs + gid) * PSTR + k0 + tid]);
            uint32_t a1 = __float_as_uint(Ps[(rs + gid + 8) * PSTR + k0 + tid]);
            uint32_t a2 = __float_as_uint(Ps[(rs + gid) * PSTR + k0 + tid + 4]);
            uint32_t a3 = __float_as_uint(Ps[(rs + gid + 8) * PSTR + k0 + tid + 4]);
#pragma unroll
            for (int nt = 0; nt < 4; nt++) {
                uint32_t b0 = __float_as_uint(Vs[(k0 + tid) * VSTR + ch + nt * 8 + gid]);
                uint32_t b1 = __float_as_uint(Vs[(k0 + tid + 4) * VSTR + ch + nt * 8 + gid]);
                mma_tf32(c[nt], a0, a1, a2, a3, b0, b1);
            }
        }
    }

    // ---- row-sum reduction -> g_psum ----
#pragma unroll
    for (int k = 0; k < 4; k++)
        red[(ry + 16 * k) * 16 + (t & 15)] = sums[k];
    __syncthreads();
    if (t < TI) {
        float s = 0.f;
#pragma unroll
        for (int q = 0; q < 16; q++) s += red[t * 16 + q];
        g_psum[sp * N + i0 + t] = s;
    }

    // ---- store unnormalized partials from mma accumulators ----
#pragma unroll
    for (int nt = 0; nt < 4; nt++) {
        const int col = ch + nt * 8 + 2 * tid;
        const int row0 = i0 + rs + gid;
        *(float2*)&g_pacc[((size_t)sp * N + row0) * OUT_F + col] =
            make_float2(c[nt][0], c[nt][1]);
        *(float2*)&g_pacc[((size_t)sp * N + row0 + 8) * OUT_F + col] =
            make_float2(c[nt][2], c[nt][3]);
    }
}

// ---------------------------------------------------------------------------
// Kernel D: combine partials, normalize, elu
// ---------------------------------------------------------------------------
__global__ void __launch_bounds__(256) combine_kernel(float* __restrict__ out) {
    const int idx = blockIdx.x * 256 + threadIdx.x;   // N*16 float4 slots
    const int r = idx >> 4;

    float4 a = make_float4(0.f, 0.f, 0.f, 0.f);
    float s = 0.f;
#pragma unroll
    for (int sp = 0; sp < SPLIT; sp++) {
        float4 p = ((const float4*)g_pacc)[(size_t)sp * (N * 16) + idx];
        a.x += p.x; a.y += p.y; a.z += p.z; a.w += p.w;
        s += g_psum[sp * N + r];
    }
    const float inv = 1.f / s;
    float v;
    float4 o;
    v = a.x * inv; o.x = (v > 0.f) ? v : expm1f(v);
    v = a.y * inv; o.y = (v > 0.f) ? v : expm1f(v);
    v = a.z * inv; o.z = (v > 0.f) ? v : expm1f(v);
    v = a.w * inv; o.w = (v > 0.f) ? v : expm1f(v);
    ((float4*)out)[idx] = o;
}

// ---------------------------------------------------------------------------
extern "C" void kernel_launch(void* const* d_in, const int* in_sizes, int n_in,
                              void* d_out, int out_size) {
    const float* h   = nullptr;
    const int*   adj = nullptr;
    const float* W   = nullptr;
    const float* a   = nullptr;
    for (int i = 0; i < n_in; i++) {
        long long sz = in_sizes[i];
        if (sz == (long long)N * IN_F)          h   = (const float*)d_in[i];
        else if (sz == (long long)N * N)        adj = (const int*)d_in[i];
        else if (sz == (long long)IN_F * OUT_F) W   = (const float*)d_in[i];
        else if (sz == 2 * OUT_F)               a   = (const float*)d_in[i];
    }

    wh_kernel<<<N / 64, 256>>>(h, W);
    attn_vec_kernel<<<N / 128, 256>>>(a);
    gat_kernel<<<dim3(N / TI, SPLIT), 256>>>(adj);
    combine_kernel<<<(N * 16) / 256, 256>>>((float*)d_out);
}

// round 9
// speedup vs baseline: 1.2494x; 1.0717x over previous
#include <cuda_runtime.h>
#include <cuda_fp16.h>
#include <cstdint>

#define N 8192
#define IN_F 512
#define OUT_F 64
#define NEG_SLOPE 0.01f
#define LOG2E 1.44269504088896340736f

#define TI 64
#define TJ 64
#define SPLIT 16
#define JSPAN (N / SPLIT)     // 512
#define NT_S (JSPAN / TJ)     // 8

#define PSW 36   // Ps row stride (words of half2): (4*gid+tid)%32 conflict-free
#define VSW 36   // Vs row stride (words of half2)

// Scratch (allocation-free rule: device globals)
__device__ __align__(16) float g_WH[N * OUT_F];
__device__ __align__(16) __half g_WHth[OUT_F * N];   // WH transposed, half
__device__ float g_wh1[N];           // pre-scaled by LOG2E
__device__ float g_wh2[N];           // pre-scaled by LOG2E
__device__ unsigned g_m2u = 0;       // order-preserving-key max of wh2L
__device__ __align__(16) float g_pacc[SPLIT * N * OUT_F];   // 32 MB partial PV
__device__ float g_psum[SPLIT * N];                         // partial row sums

__device__ __forceinline__ uint32_t su(const void* p) {
    return (uint32_t)__cvta_generic_to_shared(p);
}
#define CP_ASYNC16(dst, src) \
    asm volatile("cp.async.cg.shared.global [%0], [%1], 16;" :: "r"(dst), "l"(src))
#define CP_COMMIT() asm volatile("cp.async.commit_group;" ::: "memory")
#define CP_WAIT0()  asm volatile("cp.async.wait_group 0;" ::: "memory")

// order-preserving float<->unsigned key (monotonic under unsigned compare)
__device__ __forceinline__ unsigned f2key(float x) {
    unsigned b = __float_as_uint(x);
    return (b & 0x80000000u) ? ~b : (b | 0x80000000u);
}
__device__ __forceinline__ float key2f(unsigned u) {
    return __uint_as_float((u & 0x80000000u) ? (u & 0x7FFFFFFFu) : ~u);
}

__device__ __forceinline__ uint32_t h2u(__half2 h) { return *(uint32_t*)&h; }

// f16 m16n8k16 tensor-core mma, f32 accumulate (baseline PTX, sm_103 ok)
__device__ __forceinline__ void mma_f16(float* c, uint32_t a0, uint32_t a1,
                                        uint32_t a2, uint32_t a3,
                                        uint32_t b0, uint32_t b1) {
    asm volatile(
        "mma.sync.aligned.m16n8k16.row.col.f32.f16.f16.f32 "
        "{%0,%1,%2,%3}, {%4,%5,%6,%7}, {%8,%9}, {%0,%1,%2,%3};"
        : "+f"(c[0]), "+f"(c[1]), "+f"(c[2]), "+f"(c[3])
        : "r"(a0), "r"(a1), "r"(a2), "r"(a3), "r"(b0), "r"(b1));
}

// ---------------------------------------------------------------------------
// Kernel A: WH = h @ W; writes g_WH (f32, row-major) and g_WHth (half, transposed)
// 128 blocks x 256 threads; block tile 64x64; thread tile 4x4; packed f32x2.
// ---------------------------------------------------------------------------
#define HS 68
__global__ void __launch_bounds__(256) wh_kernel(const float* __restrict__ h,
                                                 const float* __restrict__ W) {
    __shared__ __align__(16) float Wc[64 * 64];   // Wc[k][f]    16 KB
    __shared__ __align__(16) float hT[64 * HS];   // hT[k][row]  17.4 KB

    const int t  = threadIdx.x;
    const int tx = t & 15;       // feats tx*4 .. +3
    const int ty = t >> 4;       // rows  ty*4 .. +3
    const int r0 = blockIdx.x * 64;

    unsigned long long acc[4][2];
#pragma unroll
    for (int r = 0; r < 4; r++) { acc[r][0] = 0ull; acc[r][1] = 0ull; }

    for (int kc = 0; kc < IN_F; kc += 64) {
        __syncthreads();
#pragma unroll
        for (int i = 0; i < 4; i++) {            // Wc: 1024 float4, contiguous
            int idx = t + i * 256;
            ((float4*)Wc)[idx] = ((const float4*)W)[(size_t)(kc + (idx >> 4)) * 16 + (idx & 15)];
        }
#pragma unroll
        for (int i = 0; i < 4; i++) {            // hT: transpose stage
            int idx = t + i * 256;
            int row = idx & 63, kq = idx >> 6;
            float4 hv = ((const float4*)h)[(size_t)(r0 + row) * (IN_F / 4) + (kc >> 2) + kq];
            hT[(kq * 4 + 0) * HS + row] = hv.x;
            hT[(kq * 4 + 1) * HS + row] = hv.y;
            hT[(kq * 4 + 2) * HS + row] = hv.z;
            hT[(kq * 4 + 3) * HS + row] = hv.w;
        }
        __syncthreads();
#pragma unroll 4
        for (int k = 0; k < 64; k++) {
            ulonglong2 w = *(const ulonglong2*)&Wc[k * 64 + tx * 4];
            float4 hv = *(const float4*)&hT[k * HS + ty * 4];
            unsigned long long hd;
            asm("mov.b64 %0, {%1, %1};" : "=l"(hd) : "f"(hv.x));
            asm("fma.rn.f32x2 %0, %1, %2, %0;" : "+l"(acc[0][0]) : "l"(hd), "l"(w.x));
            asm("fma.rn.f32x2 %0, %1, %2, %0;" : "+l"(acc[0][1]) : "l"(hd), "l"(w.y));
            asm("mov.b64 %0, {%1, %1};" : "=l"(hd) : "f"(hv.y));
            asm("fma.rn.f32x2 %0, %1, %2, %0;" : "+l"(acc[1][0]) : "l"(hd), "l"(w.x));
            asm("fma.rn.f32x2 %0, %1, %2, %0;" : "+l"(acc[1][1]) : "l"(hd), "l"(w.y));
            asm("mov.b64 %0, {%1, %1};" : "=l"(hd) : "f"(hv.z));
            asm("fma.rn.f32x2 %0, %1, %2, %0;" : "+l"(acc[2][0]) : "l"(hd), "l"(w.x));
            asm("fma.rn.f32x2 %0, %1, %2, %0;" : "+l"(acc[2][1]) : "l"(hd), "l"(w.y));
            asm("mov.b64 %0, {%1, %1};" : "=l"(hd) : "f"(hv.w));
            asm("fma.rn.f32x2 %0, %1, %2, %0;" : "+l"(acc[3][0]) : "l"(hd), "l"(w.x));
            asm("fma.rn.f32x2 %0, %1, %2, %0;" : "+l"(acc[3][1]) : "l"(hd), "l"(w.y));
        }
    }

    float vv[4][4];   // [r][q] = row ty*4+r, feat tx*4+q
#pragma unroll
    for (int r = 0; r < 4; r++) {
        asm("mov.b64 {%0, %1}, %2;" : "=f"(vv[r][0]), "=f"(vv[r][1]) : "l"(acc[r][0]));
        asm("mov.b64 {%0, %1}, %2;" : "=f"(vv[r][2]), "=f"(vv[r][3]) : "l"(acc[r][1]));
        *(float4*)(g_WH + (size_t)(r0 + ty * 4 + r) * OUT_F + tx * 4) =
            make_float4(vv[r][0], vv[r][1], vv[r][2], vv[r][3]);
    }
    // transposed half copy: g_WHth[f][row]
#pragma unroll
    for (int q = 0; q < 4; q++) {
        __half2 lo = __floats2half2_rn(vv[0][q], vv[1][q]);
        __half2 hi = __floats2half2_rn(vv[2][q], vv[3][q]);
        *(uint2*)(g_WHth + (size_t)(tx * 4 + q) * N + r0 + ty * 4) =
            make_uint2(h2u(lo), h2u(hi));
    }
}

// ---------------------------------------------------------------------------
// Kernel B: wh1/wh2 row dots (LOG2E-scaled) + global wh2 max via key-atomicMax
// ---------------------------------------------------------------------------
__global__ void __launch_bounds__(256) attn_vec_kernel(const float* __restrict__ a) {
    __shared__ float s2[8];
    const int warp = threadIdx.x >> 5;
    const int lane = threadIdx.x & 31;

    const float a1a = a[2 * lane], a1b = a[2 * lane + 1];
    const float a2a = a[OUT_F + 2 * lane], a2b = a[OUT_F + 2 * lane + 1];

    float m2 = -1e30f;
#pragma unroll
    for (int rr = 0; rr < 16; rr++) {
        const int r = blockIdx.x * 128 + rr * 8 + warp;
        float2 v = ((const float2*)(g_WH + (size_t)r * OUT_F))[lane];
        float d1 = v.x * a1a + v.y * a1b;
        float d2 = v.x * a2a + v.y * a2b;
#pragma unroll
        for (int off = 16; off > 0; off >>= 1) {
            d1 += __shfl_xor_sync(0xFFFFFFFFu, d1, off);
            d2 += __shfl_xor_sync(0xFFFFFFFFu, d2, off);
        }
        d1 *= LOG2E; d2 *= LOG2E;
        if (lane == 0) {
            g_wh1[r] = d1;
            g_wh2[r] = d2;
            m2 = fmaxf(m2, d2);
        }
    }
    if (lane == 0) s2[warp] = m2;
    __syncthreads();
    if (threadIdx.x == 0) {
        float b2 = s2[0];
#pragma unroll
        for (int w = 1; w < 8; w++) b2 = fmaxf(b2, s2[w]);
        atomicMax(&g_m2u, f2key(b2));   // idempotent across graph replays
    }
}

// ---------------------------------------------------------------------------
// Kernel C: scores (SIMT, exp2, per-row shift) -> PV matmul (f16 m16n8k16)
//  grid (N/TI, SPLIT) = (128, 16). Warp w: rows (w>>1)*16..+16, cols (w&1)*32..+32.
// ---------------------------------------------------------------------------
__global__ void __launch_bounds__(256, 3) gat_kernel(const int* __restrict__ adj) {
    __shared__ __align__(16) uint32_t Ps[TI * PSW];   // 9 KB  P as half2
    __shared__ __align__(16) uint32_t Vs[TJ * VSW];   // 9 KB  Vt as half2 (n-major)
    __shared__ __align__(16) float wh2s[2][TJ];
    __shared__ float wh1s[TI];
    __shared__ float shs[TI];      // per-row log2-domain shift
    __shared__ float red[TI * 16];

    const int t    = threadIdx.x;
    const int ry   = t >> 4;            // score rows: ry + 16k
    const int tx   = t & 15;
    const int jb   = tx * 4;            // score cols within tile
    const int lane = t & 31;
    const int warp = t >> 5;
    const int gid  = lane >> 2;
    const int tid  = lane & 3;
    const int rs   = (warp >> 1) * 16;  // mma row stripe
    const int ch   = (warp & 1) * 32;   // mma col half
    const int i0   = blockIdx.x * TI;
    const int sp   = blockIdx.y;
    const int jbase = sp * JSPAN;

    const float m2L = key2f(g_m2u);
    if (t < TI) {
        float w1 = g_wh1[i0 + t];
        wh1s[t] = w1;
        float sh = w1 + m2L;
        shs[t] = (sh > 0.f) ? sh : NEG_SLOPE * sh;   // = row max in log2 domain
    }
    if (t < 16) CP_ASYNC16(su(&wh2s[0][t * 4]), (const void*)(g_wh2 + jbase + t * 4));
    CP_COMMIT();

    int4 a4[4];
#pragma unroll
    for (int k = 0; k < 4; k++)
        a4[k] = *(const int4*)(adj + (size_t)(i0 + ry + 16 * k) * N + jbase + jb);

    float sums[4] = {0.f, 0.f, 0.f, 0.f};
    float c[4][4];
#pragma unroll
    for (int nt = 0; nt < 4; nt++)
#pragma unroll
        for (int q = 0; q < 4; q++) c[nt][q] = 0.f;

    CP_WAIT0();   // wh2s[0] resident (visibility via first in-loop sync)

    for (int tt = 0; tt < NT_S; ++tt) {
        const int b = tt & 1;
        const int j0 = jbase + tt * TJ;
        __syncthreads();   // mma(tt-1) done -> Ps/Vs free; wh2s[b]/wh1s/shs visible

        // ---- issue Vt tile (tt): 64 f-rows x 64 half = 512 x 16B chunks ----
#pragma unroll
        for (int i = 0; i < 2; i++) {
            int idx = t + i * 256;
            int f = idx >> 3, cc = idx & 7;
            CP_ASYNC16(su(Vs) + f * (VSW * 4) + cc * 16,
                       (const void*)(g_WHth + (size_t)f * N + j0 + cc * 8));
        }
        if (tt + 1 < NT_S && t < 16)
            CP_ASYNC16(su(&wh2s[b ^ 1][t * 4]), (const void*)(g_wh2 + j0 + TJ + t * 4));
        CP_COMMIT();

        // ---- scores -> Ps (half2), register row sums, adjacency prefetch ----
        const float4 w2 = *(const float4*)&wh2s[b][jb];
#pragma unroll
        for (int k = 0; k < 4; k++) {
            const int r = ry + 16 * k;
            const float b1 = wh1s[r];
            const float sh = shs[r];
            float e0 = b1 + w2.x; e0 = (e0 > 0.f) ? e0 : NEG_SLOPE * e0;
            float e1 = b1 + w2.y; e1 = (e1 > 0.f) ? e1 : NEG_SLOPE * e1;
            float e2 = b1 + w2.z; e2 = (e2 > 0.f) ? e2 : NEG_SLOPE * e2;
            float e3 = b1 + w2.w; e3 = (e3 > 0.f) ? e3 : NEG_SLOPE * e3;
            float p0 = (a4[k].x > 0) ? exp2f(e0 - sh) : 0.f;
            float p1 = (a4[k].y > 0) ? exp2f(e1 - sh) : 0.f;
            float p2 = (a4[k].z > 0) ? exp2f(e2 - sh) : 0.f;
            float p3 = (a4[k].w > 0) ? exp2f(e3 - sh) : 0.f;
            sums[k] += (p0 + p1) + (p2 + p3);
            __half2 h01 = __floats2half2_rn(p0, p1);
            __half2 h23 = __floats2half2_rn(p2, p3);
            *(uint2*)&Ps[r * PSW + tx * 2] = make_uint2(h2u(h01), h2u(h23));
            if (tt + 1 < NT_S)
                a4[k] = *(const int4*)(adj + (size_t)(i0 + r) * N + j0 + TJ + jb);
        }

        CP_WAIT0();
        __syncthreads();   // Ps + Vs ready

        // ---- tensor-core PV: per warp 16x32 output, k=64 in 4 k16 chunks ----
#pragma unroll
        for (int kc = 0; kc < 4; kc++) {
            const int k0 = kc * 8;   // word offset within row
            uint32_t a0 = Ps[(rs + gid) * PSW + k0 + tid];
            uint32_t a1 = Ps[(rs + gid + 8) * PSW + k0 + tid];
            uint32_t a2 = Ps[(rs + gid) * PSW + k0 + tid + 4];
            uint32_t a3 = Ps[(rs + gid + 8) * PSW + k0 + tid + 4];
#pragma unroll
            for (int nt = 0; nt < 4; nt++) {
                const int n = ch + nt * 8 + gid;
                uint32_t b0 = Vs[n * VSW + k0 + tid];
                uint32_t b1 = Vs[n * VSW + k0 + tid + 4];
                mma_f16(c[nt], a0, a1, a2, a3, b0, b1);
            }
        }
    }

    // ---- row-sum reduction -> g_psum ----
#pragma unroll
    for (int k = 0; k < 4; k++)
        red[(ry + 16 * k) * 16 + tx] = sums[k];
    __syncthreads();
    if (t < TI) {
        float s = 0.f;
#pragma unroll
        for (int q = 0; q < 16; q++) s += red[t * 16 + q];
        g_psum[sp * N + i0 + t] = s;
    }

    // ---- store unnormalized partials from mma accumulators ----
#pragma unroll
    for (int nt = 0; nt < 4; nt++) {
        const int col = ch + nt * 8 + 2 * tid;
        const int row0 = i0 + rs + gid;
        *(float2*)&g_pacc[((size_t)sp * N + row0) * OUT_F + col] =
            make_float2(c[nt][0], c[nt][1]);
        *(float2*)&g_pacc[((size_t)sp * N + row0 + 8) * OUT_F + col] =
            make_float2(c[nt][2], c[nt][3]);
    }
}

// ---------------------------------------------------------------------------
// Kernel D: combine partials, normalize, elu
// ---------------------------------------------------------------------------
__global__ void __launch_bounds__(256) combine_kernel(float* __restrict__ out) {
    const int idx = blockIdx.x * 256 + threadIdx.x;   // N*16 float4 slots
    const int r = idx >> 4;

    float4 a = make_float4(0.f, 0.f, 0.f, 0.f);
    float s = 0.f;
#pragma unroll
    for (int sp = 0; sp < SPLIT; sp++) {
        float4 p = ((const float4*)g_pacc)[(size_t)sp * (N * 16) + idx];
        a.x += p.x; a.y += p.y; a.z += p.z; a.w += p.w;
        s += g_psum[sp * N + r];
    }
    const float inv = 1.f / s;
    float v;
    float4 o;
    v = a.x * inv; o.x = (v > 0.f) ? v : expm1f(v);
    v = a.y * inv; o.y = (v > 0.f) ? v : expm1f(v);
    v = a.z * inv; o.z = (v > 0.f) ? v : expm1f(v);
    v = a.w * inv; o.w = (v > 0.f) ? v : expm1f(v);
    ((float4*)out)[idx] = o;
}

// ---------------------------------------------------------------------------
extern "C" void kernel_launch(void* const* d_in, const int* in_sizes, int n_in,
                              void* d_out, int out_size) {
    const float* h   = nullptr;
    const int*   adj = nullptr;
    const float* W   = nullptr;
    const float* a   = nullptr;
    for (int i = 0; i < n_in; i++) {
        long long sz = in_sizes[i];
        if (sz == (long long)N * IN_F)          h   = (const float*)d_in[i];
        else if (sz == (long long)N * N)        adj = (const int*)d_in[i];
        else if (sz == (long long)IN_F * OUT_F) W   = (const float*)d_in[i];
        else if (sz == 2 * OUT_F)               a   = (const float*)d_in[i];
    }

    wh_kernel<<<N / 64, 256>>>(h, W);
    attn_vec_kernel<<<N / 128, 256>>>(a);
    gat_kernel<<<dim3(N / TI, SPLIT), 256>>>(adj);
    combine_kernel<<<(N * 16) / 256, 256>>>((float*)d_out);
}